// round 6
// baseline (speedup 1.0000x reference)
#include <cuda_runtime.h>
#include <cuda_fp16.h>
#include <math.h>
#include <stdint.h>

#define NN 50000
#define NE 800000
#define DI 128

// ---------------- device scratch ----------------
__device__ float  g_B1[NN * 128];    // gemm1 out (fp32); reused as gemm2 out (64-wide)
__device__ __half g_Yh[NN * 128];    // layer1 activation, fp16 hi
__device__ __half g_Yl[NN * 128];    // layer1 activation, fp16 lo (residual)
__device__ float  g_dis[NN];
__device__ int    g_cnt[NN];
__device__ int    g_off[NN + 1];
__device__ int    g_cur[NN];
__device__ int2   g_edge[NE];        // {src, __float_as_int(dis[src])}
// W images: fp16 split, [n][k] row-major, stride 136 halves; hi tile then lo tile
__device__ __align__(16) __half g_W1img[2 * 128 * 136];
__device__ __align__(16) __half g_W2img[2 * 64 * 136];

__device__ __forceinline__ uint32_t smem_u32(const void* p) {
    uint32_t a;
    asm("{ .reg .u64 t; cvta.to.shared.u64 t, %1; cvt.u32.u64 %0, t; }" : "=r"(a) : "l"(p));
    return a;
}

#define LDSM_X4(r0, r1, r2, r3, addr) \
    asm volatile("ldmatrix.sync.aligned.m8n8.x4.shared.b16 {%0,%1,%2,%3}, [%4];" \
                 : "=r"(r0), "=r"(r1), "=r"(r2), "=r"(r3) : "r"(addr))
#define LDSM_X2(r0, r1, addr) \
    asm volatile("ldmatrix.sync.aligned.m8n8.x2.shared.b16 {%0,%1}, [%2];" \
                 : "=r"(r0), "=r"(r1) : "r"(addr))

__device__ __forceinline__ void mma16816(float* c, const uint32_t* a, const uint32_t* b) {
    asm volatile(
        "mma.sync.aligned.m16n8k16.row.col.f32.f16.f16.f32 "
        "{%0,%1,%2,%3}, {%4,%5,%6,%7}, {%8,%9}, {%0,%1,%2,%3};"
        : "+f"(c[0]), "+f"(c[1]), "+f"(c[2]), "+f"(c[3])
        : "r"(a[0]), "r"(a[1]), "r"(a[2]), "r"(a[3]), "r"(b[0]), "r"(b[1]));
}

// ---------------- W image precompute (both weights, one launch) ----------------
__global__ void k_wconv_all(const float* __restrict__ W1, const float* __restrict__ W2,
                            __half* __restrict__ img1, __half* __restrict__ img2) {
    const int S = 136;
    int b = blockIdx.x;
    if (b < 32) {
        // W1: 128x128
        for (int idx = b * 256 + threadIdx.x; idx < 128 * 128; idx += 32 * 256) {
            int nn = idx % 128, k = idx / 128;
            float v = W1[k * 128 + nn];
            __half h = __float2half_rn(v);
            __half l = __float2half_rn(v - __half2float(h));
            img1[nn * S + k] = h;
            img1[128 * S + nn * S + k] = l;
        }
    } else {
        // W2: 128x64
        for (int idx = (b - 32) * 256 + threadIdx.x; idx < 64 * 128; idx += 16 * 256) {
            int nn = idx % 64, k = idx / 64;
            float v = W2[k * 64 + nn];
            __half h = __float2half_rn(v);
            __half l = __float2half_rn(v - __half2float(h));
            img2[nn * S + k] = h;
            img2[64 * S + nn * S + k] = l;
        }
    }
}

// ---------------- tensor GEMM via mma.sync, 3-term fp16 split, 64-row tiles ----------------
// PRESPLIT=false: A fp32 (Af), split on stage. PRESPLIT=true: A pre-split (Ahs/Als halves).
template<int NOUT, bool PRESPLIT>
__global__ void __launch_bounds__(256) k_mgemm(const float* __restrict__ Af,
                                               const __half* __restrict__ Ahs,
                                               const __half* __restrict__ Als,
                                               const __half* __restrict__ Wimg,
                                               float* __restrict__ outp, int n) {
    constexpr int S  = 136;
    constexpr int SB = S * 2;
    constexpr int ASZ = 64 * S;
    constexpr int BSZ = NOUT * S;
    constexpr int MI = (NOUT == 128) ? 2 : 1;   // m16 frags per warp
    constexpr int NJ = 4;                       // n8 frags per warp

    extern __shared__ __half sm[];
    __half* Ah = sm;
    __half* Al = sm + ASZ;
    __half* Bh = sm + 2 * ASZ;
    // Bl = Bh + BSZ (contiguous with image layout)

    int tid = threadIdx.x, wid = tid >> 5, lane = tid & 31;
    int row0 = blockIdx.x * 64;

    // stage W images (hi+lo contiguous, rows 16B-aligned since 272 % 16 == 0)
    {
        const uint4* src = (const uint4*)Wimg;
        uint4* dst = (uint4*)Bh;
        for (int i = tid; i < (2 * BSZ) / 8; i += 256) dst[i] = src[i];
    }
    if (PRESPLIT) {
        // 64 rows x 16 uint4 per tile
        for (int i = tid; i < 1024; i += 256) {
            int r = i >> 4, c = i & 15;
            uint4 vh = make_uint4(0, 0, 0, 0), vl = make_uint4(0, 0, 0, 0);
            if (row0 + r < n) {
                vh = __ldg((const uint4*)&Ahs[(size_t)(row0 + r) * 128 + c * 8]);
                vl = __ldg((const uint4*)&Als[(size_t)(row0 + r) * 128 + c * 8]);
            }
            *(uint4*)&Ah[r * S + c * 8] = vh;
            *(uint4*)&Al[r * S + c * 8] = vl;
        }
    } else {
        const float4* A4 = (const float4*)Af;
        #pragma unroll
        for (int i = 0; i < 8; i++) {
            int idx = tid + i * 256;          // 0..2047: 64 rows x 32 float4
            int r = idx >> 5, c = idx & 31;
            float4 v = make_float4(0.f, 0.f, 0.f, 0.f);
            if (row0 + r < n) v = A4[(size_t)(row0 + r) * 32 + c];
            __half h0 = __float2half_rn(v.x), h1 = __float2half_rn(v.y);
            __half h2 = __float2half_rn(v.z), h3 = __float2half_rn(v.w);
            __half l0 = __float2half_rn(v.x - __half2float(h0));
            __half l1 = __float2half_rn(v.y - __half2float(h1));
            __half l2 = __float2half_rn(v.z - __half2float(h2));
            __half l3 = __float2half_rn(v.w - __half2float(h3));
            __half2 hp0 = __halves2half2(h0, h1), hp1 = __halves2half2(h2, h3);
            __half2 lp0 = __halves2half2(l0, l1), lp1 = __halves2half2(l2, l3);
            *(uint2*)&Ah[r * S + c * 4] = make_uint2(*(uint32_t*)&hp0, *(uint32_t*)&hp1);
            *(uint2*)&Al[r * S + c * 4] = make_uint2(*(uint32_t*)&lp0, *(uint32_t*)&lp1);
        }
    }
    __syncthreads();

    // warp tiling
    int m0w, n0w;
    if (NOUT == 128) { m0w = (wid >> 2) * 32; n0w = (wid & 3) * 32; }
    else             { m0w = (wid >> 1) * 16; n0w = (wid & 1) * 32; }

    float acc[MI][NJ][4] = {};

    uint32_t aAh = smem_u32(Ah), aAl = smem_u32(Al);
    uint32_t aBh = smem_u32(Bh), aBl = aBh + BSZ * 2;
    uint32_t a_lane = (uint32_t)(m0w + (lane & 15)) * SB + ((lane >> 4) << 4);
    int bl = lane & 15;
    uint32_t b_lane = (uint32_t)(n0w + (bl & 7)) * SB + ((bl >> 3) << 4);

    #pragma unroll
    for (int t = 0; t < 3; t++) {
        uint32_t aA = (t == 2) ? aAl : aAh;
        uint32_t aB = (t == 1) ? aBl : aBh;
        #pragma unroll
        for (int k0 = 0; k0 < 128; k0 += 16) {
            uint32_t ar[MI][4];
            #pragma unroll
            for (int mi = 0; mi < MI; mi++) {
                uint32_t ad = aA + a_lane + (uint32_t)(mi * 16) * SB + k0 * 2;
                LDSM_X4(ar[mi][0], ar[mi][1], ar[mi][2], ar[mi][3], ad);
            }
            #pragma unroll
            for (int nj = 0; nj < NJ; nj++) {
                uint32_t br[2];
                uint32_t bd = aB + b_lane + (uint32_t)(nj * 8) * SB + k0 * 2;
                LDSM_X2(br[0], br[1], bd);
                #pragma unroll
                for (int mi = 0; mi < MI; mi++) mma16816(acc[mi][nj], ar[mi], br);
            }
        }
    }

    // epilogue
    #pragma unroll
    for (int mi = 0; mi < MI; mi++) {
        int r = row0 + m0w + mi * 16 + (lane >> 2);
        #pragma unroll
        for (int nj = 0; nj < NJ; nj++) {
            int c = n0w + nj * 8 + (lane & 3) * 2;
            if (r < n)
                *(float2*)&outp[(size_t)r * NOUT + c] = make_float2(acc[mi][nj][0], acc[mi][nj][1]);
            if (r + 8 < n)
                *(float2*)&outp[(size_t)(r + 8) * NOUT + c] = make_float2(acc[mi][nj][2], acc[mi][nj][3]);
        }
    }
}

// ---------------- CSR build ----------------
__global__ void k_hist(const int* __restrict__ col, int e4) {
    int i = blockIdx.x * blockDim.x + threadIdx.x;
    if (i < e4) {
        int4 c = ((const int4*)col)[i];
        atomicAdd(&g_cnt[c.x], 1);
        atomicAdd(&g_cnt[c.y], 1);
        atomicAdd(&g_cnt[c.z], 1);
        atomicAdd(&g_cnt[c.w], 1);
    }
}

__global__ void k_scan(int n, int e) {
    __shared__ int sbuf[1024];
    int tid = threadIdx.x;
    const int CH = (n + 1023) / 1024;
    int beg = tid * CH;
    int end = beg + CH; if (end > n) end = n;
    int sum = 0;
    for (int i = beg; i < end; i++) sum += g_cnt[i];
    sbuf[tid] = sum;
    __syncthreads();
    for (int d = 1; d < 1024; d <<= 1) {
        int t = (tid >= d) ? sbuf[tid - d] : 0;
        __syncthreads();
        sbuf[tid] += t;
        __syncthreads();
    }
    int base = sbuf[tid] - sum;
    for (int i = beg; i < end; i++) {
        int c = g_cnt[i];
        g_off[i] = base;
        g_cur[i] = base;
        g_dis[i] = rsqrtf((float)(c + 1));
        base += c;
    }
    if (tid == 0) g_off[n] = e;
}

__global__ void k_place(const int* __restrict__ row, const int* __restrict__ col, int e4) {
    int i = blockIdx.x * blockDim.x + threadIdx.x;
    if (i < e4) {
        int4 r4 = ((const int4*)row)[i];
        int4 c4 = ((const int4*)col)[i];
        int p;
        p = atomicAdd(&g_cur[c4.x], 1);
        g_edge[p] = make_int2(r4.x, __float_as_int(g_dis[r4.x]));
        p = atomicAdd(&g_cur[c4.y], 1);
        g_edge[p] = make_int2(r4.y, __float_as_int(g_dis[r4.y]));
        p = atomicAdd(&g_cur[c4.z], 1);
        g_edge[p] = make_int2(r4.z, __float_as_int(g_dis[r4.z]));
        p = atomicAdd(&g_cur[c4.w], 1);
        g_edge[p] = make_int2(r4.w, __float_as_int(g_dis[r4.w]));
    }
}

// ---------------- gather layer1 (warp per node, 128-wide), fp16-split output ----------------
__global__ void k_gather128(const float* __restrict__ hs, const float* __restrict__ bias,
                            __half* __restrict__ Yh, __half* __restrict__ Yl, int n) {
    int w = (blockIdx.x * blockDim.x + threadIdx.x) >> 5;
    if (w >= n) return;
    int lane = threadIdx.x & 31;
    const float4* hs4 = (const float4*)hs;
    float dw = g_dis[w];
    float4 self = hs4[(size_t)w * 32 + lane];
    float4 acc = make_float4(self.x * dw, self.y * dw, self.z * dw, self.w * dw);
    int s = g_off[w], e = g_off[w + 1];
    int j = s;
    for (; j + 8 <= e; j += 8) {
        int2 ed[8];
        #pragma unroll
        for (int i = 0; i < 8; i++) ed[i] = __ldg(&g_edge[j + i]);
        #pragma unroll
        for (int i = 0; i < 8; i++) {
            float d = __int_as_float(ed[i].y);
            float4 m = hs4[(size_t)ed[i].x * 32 + lane];
            acc.x = fmaf(d, m.x, acc.x);
            acc.y = fmaf(d, m.y, acc.y);
            acc.z = fmaf(d, m.z, acc.z);
            acc.w = fmaf(d, m.w, acc.w);
        }
    }
    for (; j < e; j++) {
        int2 ed = __ldg(&g_edge[j]);
        float d = __int_as_float(ed.y);
        float4 m = hs4[(size_t)ed.x * 32 + lane];
        acc.x = fmaf(d, m.x, acc.x);
        acc.y = fmaf(d, m.y, acc.y);
        acc.z = fmaf(d, m.z, acc.z);
        acc.w = fmaf(d, m.w, acc.w);
    }
    float4 b = ((const float4*)bias)[lane];
    float4 o = make_float4(fmaxf(acc.x * dw + b.x, 0.f), fmaxf(acc.y * dw + b.y, 0.f),
                           fmaxf(acc.z * dw + b.z, 0.f), fmaxf(acc.w * dw + b.w, 0.f));
    // fp16 split output
    __half h0 = __float2half_rn(o.x), h1 = __float2half_rn(o.y);
    __half h2 = __float2half_rn(o.z), h3 = __float2half_rn(o.w);
    __half l0 = __float2half_rn(o.x - __half2float(h0));
    __half l1 = __float2half_rn(o.y - __half2float(h1));
    __half l2 = __float2half_rn(o.z - __half2float(h2));
    __half l3 = __float2half_rn(o.w - __half2float(h3));
    __half2 hp0 = __halves2half2(h0, h1), hp1 = __halves2half2(h2, h3);
    __half2 lp0 = __halves2half2(l0, l1), lp1 = __halves2half2(l2, l3);
    size_t base = (size_t)w * 128 + lane * 4;
    *(uint2*)&Yh[base] = make_uint2(*(uint32_t*)&hp0, *(uint32_t*)&hp1);
    *(uint2*)&Yl[base] = make_uint2(*(uint32_t*)&lp0, *(uint32_t*)&lp1);
}

// ---------------- gather layer2 (warp per node, 64-wide) ----------------
__global__ void k_gather64(const float* __restrict__ hs, const float* __restrict__ bias,
                           float* __restrict__ outp, int n) {
    int w = (blockIdx.x * blockDim.x + threadIdx.x) >> 5;
    if (w >= n) return;
    int lane = threadIdx.x & 31;
    const float2* hs2 = (const float2*)hs;
    float dw = g_dis[w];
    float2 self = hs2[(size_t)w * 32 + lane];
    float2 acc = make_float2(self.x * dw, self.y * dw);
    int s = g_off[w], e = g_off[w + 1];
    int j = s;
    for (; j + 8 <= e; j += 8) {
        int2 ed[8];
        #pragma unroll
        for (int i = 0; i < 8; i++) ed[i] = __ldg(&g_edge[j + i]);
        #pragma unroll
        for (int i = 0; i < 8; i++) {
            float d = __int_as_float(ed[i].y);
            float2 m = hs2[(size_t)ed[i].x * 32 + lane];
            acc.x = fmaf(d, m.x, acc.x);
            acc.y = fmaf(d, m.y, acc.y);
        }
    }
    for (; j < e; j++) {
        int2 ed = __ldg(&g_edge[j]);
        float d = __int_as_float(ed.y);
        float2 m = hs2[(size_t)ed.x * 32 + lane];
        acc.x = fmaf(d, m.x, acc.x);
        acc.y = fmaf(d, m.y, acc.y);
    }
    float2 b = ((const float2*)bias)[lane];
    float2 o = make_float2(acc.x * dw + b.x, acc.y * dw + b.y);
    ((float2*)outp)[(size_t)w * 32 + lane] = o;
}

// ---------------- launch ----------------
extern "C" void kernel_launch(void* const* d_in, const int* in_sizes, int n_in,
                              void* d_out, int out_size) {
    const float* x   = (const float*)d_in[0];
    const int*   ei  = (const int*)d_in[1];
    const float* W1  = (const float*)d_in[2];
    const float* b1  = (const float*)d_in[3];
    const float* W2  = (const float*)d_in[4];
    const float* b2  = (const float*)d_in[5];
    float* out = (float*)d_out;

    const int n = in_sizes[0] / DI;     // 50000
    const int e = in_sizes[1] / 2;      // 800000
    const int* row = ei;
    const int* col = ei + e;

    float* B1; int* cnt; __half *W1img, *W2img, *Yh, *Yl;
    cudaGetSymbolAddress((void**)&B1, g_B1);
    cudaGetSymbolAddress((void**)&cnt, g_cnt);
    cudaGetSymbolAddress((void**)&W1img, g_W1img);
    cudaGetSymbolAddress((void**)&W2img, g_W2img);
    cudaGetSymbolAddress((void**)&Yh, g_Yh);
    cudaGetSymbolAddress((void**)&Yl, g_Yl);

    const int SM1 = (2 * 64 * 136 + 2 * 128 * 136) * 2;   // 104448
    const int SM2 = (2 * 64 * 136 + 2 * 64 * 136) * 2;    // 69632
    cudaFuncSetAttribute((const void*)k_mgemm<128, false>,
                         cudaFuncAttributeMaxDynamicSharedMemorySize, SM1);
    cudaFuncSetAttribute((const void*)k_mgemm<64, true>,
                         cudaFuncAttributeMaxDynamicSharedMemorySize, SM2);

    cudaStream_t s1;
    cudaStreamCreate(&s1);
    cudaEvent_t evFork, evJoin;
    cudaEventCreateWithFlags(&evFork, cudaEventDisableTiming);
    cudaEventCreateWithFlags(&evJoin, cudaEventDisableTiming);

    int nblk = (n + 63) / 64;   // 782

    // side stream: W conversion + GEMM1
    cudaEventRecord(evFork, 0);
    cudaStreamWaitEvent(s1, evFork, 0);
    k_wconv_all<<<48, 256, 0, s1>>>(W1, W2, W1img, W2img);
    k_mgemm<128, false><<<nblk, 256, SM1, s1>>>(x, nullptr, nullptr, W1img, B1, n);
    cudaEventRecord(evJoin, s1);

    // capture stream: CSR build
    cudaMemsetAsync(cnt, 0, n * sizeof(int));
    int e4 = e / 4;
    k_hist<<<(e4 + 255) / 256, 256>>>(col, e4);
    k_scan<<<1, 1024>>>(n, e);
    k_place<<<(e4 + 255) / 256, 256>>>(row, col, e4);

    cudaStreamWaitEvent(0, evJoin, 0);
    k_gather128<<<(n * 32 + 255) / 256, 256>>>(B1, b1, Yh, Yl, n);
    k_mgemm<64, true><<<nblk, 256, SM2>>>(nullptr, Yh, Yl, W2img, B1, n);
    k_gather64<<<(n * 32 + 255) / 256, 256>>>(B1, b2, out, n);

    cudaStreamDestroy(s1);
    cudaEventDestroy(evFork);
    cudaEventDestroy(evJoin);
}

// round 7
// speedup vs baseline: 1.4277x; 1.4277x over previous
#include <cuda_runtime.h>
#include <cuda_fp16.h>
#include <math.h>
#include <stdint.h>

#define NN 50000
#define NE 800000
#define DI 128

// ---------------- device scratch ----------------
__device__ float g_B1[NN * 128];   // hidden h = A@W (unscaled)
__device__ float g_B2[NN * 128];   // y1
__device__ float g_dis[NN];
__device__ int   g_cnt[NN];
__device__ int   g_off[NN + 1];
__device__ int   g_cur[NN];
__device__ int   g_src[NE];
__device__ int   g_bsum[64];       // per-chunk sums
__device__ int   g_bbase[64];      // exclusive chunk bases
// W images: fp16 split, [n][k] row-major, stride 136 halves; hi tile then lo tile
__device__ __align__(16) __half g_W1img[2 * 128 * 136];
__device__ __align__(16) __half g_W2img[2 * 64 * 136];

__device__ __forceinline__ uint32_t smem_u32(const void* p) {
    uint32_t a;
    asm("{ .reg .u64 t; cvta.to.shared.u64 t, %1; cvt.u32.u64 %0, t; }" : "=r"(a) : "l"(p));
    return a;
}

#define LDSM_X4(r0, r1, r2, r3, addr) \
    asm volatile("ldmatrix.sync.aligned.m8n8.x4.shared.b16 {%0,%1,%2,%3}, [%4];" \
                 : "=r"(r0), "=r"(r1), "=r"(r2), "=r"(r3) : "r"(addr))
#define LDSM_X2(r0, r1, addr) \
    asm volatile("ldmatrix.sync.aligned.m8n8.x2.shared.b16 {%0,%1}, [%2];" \
                 : "=r"(r0), "=r"(r1) : "r"(addr))

__device__ __forceinline__ void mma16816(float* c, const uint32_t* a, const uint32_t* b) {
    asm volatile(
        "mma.sync.aligned.m16n8k16.row.col.f32.f16.f16.f32 "
        "{%0,%1,%2,%3}, {%4,%5,%6,%7}, {%8,%9}, {%0,%1,%2,%3};"
        : "+f"(c[0]), "+f"(c[1]), "+f"(c[2]), "+f"(c[3])
        : "r"(a[0]), "r"(a[1]), "r"(a[2]), "r"(a[3]), "r"(b[0]), "r"(b[1]));
}

// ---------------- W image precompute ----------------
template<int NOUT>
__global__ void k_wconv(const float* __restrict__ W, __half* __restrict__ img) {
    constexpr int S = 136;
    int tid = threadIdx.x;
    for (int idx = tid; idx < NOUT * 128; idx += 256) {
        int nn = idx % NOUT;     // output col = B row
        int k  = idx / NOUT;     // K index
        float v = W[k * NOUT + nn];
        __half h = __float2half_rn(v);
        __half l = __float2half_rn(v - __half2float(h));
        img[nn * S + k] = h;
        img[NOUT * S + nn * S + k] = l;
    }
}

// ---------------- tensor GEMM via mma.sync, 3-term fp16 split (R5 known-good) ----------------
template<int NOUT>
__global__ void __launch_bounds__(256, 1) k_mgemm(const float* __restrict__ A,
                                                  const __half* __restrict__ Wimg,
                                                  float* __restrict__ outp, int n) {
    constexpr int S = 136;
    constexpr int SB = S * 2;
    constexpr int ASZ = 128 * S;
    constexpr int BSZ = NOUT * S;
    constexpr int MI = (NOUT == 128) ? 4 : 2;

    extern __shared__ __half sm[];
    __half* Ah = sm;
    __half* Al = sm + ASZ;
    __half* Bh = sm + 2 * ASZ;
    __half* Bl = sm + 2 * ASZ + BSZ;

    int tid = threadIdx.x, wid = tid >> 5, lane = tid & 31;
    int row0 = blockIdx.x * 128;

    {
        const uint4* src = (const uint4*)Wimg;
        uint4* dst = (uint4*)Bh;
        for (int i = tid; i < (2 * BSZ) / 8; i += 256) dst[i] = src[i];
    }
    {
        const float4* A4 = (const float4*)A;
        #pragma unroll
        for (int i = 0; i < 16; i++) {
            int idx = tid + i * 256;
            int r = idx >> 5;
            int c = idx & 31;
            float4 v = make_float4(0.f, 0.f, 0.f, 0.f);
            if (row0 + r < n) v = A4[(size_t)(row0 + r) * 32 + c];
            __half h0 = __float2half_rn(v.x), h1 = __float2half_rn(v.y);
            __half h2 = __float2half_rn(v.z), h3 = __float2half_rn(v.w);
            __half l0 = __float2half_rn(v.x - __half2float(h0));
            __half l1 = __float2half_rn(v.y - __half2float(h1));
            __half l2 = __float2half_rn(v.z - __half2float(h2));
            __half l3 = __float2half_rn(v.w - __half2float(h3));
            __half2 hp0 = __halves2half2(h0, h1), hp1 = __halves2half2(h2, h3);
            __half2 lp0 = __halves2half2(l0, l1), lp1 = __halves2half2(l2, l3);
            *(uint2*)&Ah[r * S + c * 4] = make_uint2(*(uint32_t*)&hp0, *(uint32_t*)&hp1);
            *(uint2*)&Al[r * S + c * 4] = make_uint2(*(uint32_t*)&lp0, *(uint32_t*)&lp1);
        }
    }
    __syncthreads();

    int m0w, n0w;
    if (NOUT == 128) { m0w = (wid >> 2) * 64; n0w = (wid & 3) * 32; }
    else             { m0w = (wid >> 1) * 32; n0w = (wid & 1) * 32; }

    float acc[MI][4][4] = {};

    uint32_t aAh = smem_u32(Ah), aAl = smem_u32(Al);
    uint32_t aBh = smem_u32(Bh), aBl = smem_u32(Bl);
    uint32_t a_lane = (uint32_t)(m0w + (lane & 15)) * SB + ((lane >> 4) << 4);
    int bl = lane & 15;
    uint32_t b_lane = (uint32_t)(n0w + (bl & 7)) * SB + ((bl >> 3) << 4);

    #pragma unroll
    for (int t = 0; t < 3; t++) {
        uint32_t aA = (t == 2) ? aAl : aAh;
        uint32_t aB = (t == 1) ? aBl : aBh;
        #pragma unroll
        for (int k0 = 0; k0 < 128; k0 += 16) {
            uint32_t ar[MI][4];
            #pragma unroll
            for (int mi = 0; mi < MI; mi++) {
                uint32_t ad = aA + a_lane + (uint32_t)(mi * 16) * SB + k0 * 2;
                LDSM_X4(ar[mi][0], ar[mi][1], ar[mi][2], ar[mi][3], ad);
            }
            #pragma unroll
            for (int nj = 0; nj < 4; nj++) {
                uint32_t br[2];
                uint32_t bd = aB + b_lane + (uint32_t)(nj * 8) * SB + k0 * 2;
                LDSM_X2(br[0], br[1], bd);
                #pragma unroll
                for (int mi = 0; mi < MI; mi++) mma16816(acc[mi][nj], ar[mi], br);
            }
        }
    }

    #pragma unroll
    for (int mi = 0; mi < MI; mi++) {
        int r = row0 + m0w + mi * 16 + (lane >> 2);
        #pragma unroll
        for (int nj = 0; nj < 4; nj++) {
            int c = n0w + nj * 8 + (lane & 3) * 2;
            if (r < n)
                *(float2*)&outp[(size_t)r * NOUT + c] = make_float2(acc[mi][nj][0], acc[mi][nj][1]);
            if (r + 8 < n)
                *(float2*)&outp[(size_t)(r + 8) * NOUT + c] = make_float2(acc[mi][nj][2], acc[mi][nj][3]);
        }
    }
}

// ---------------- CSR build: hist + 3-phase parallel scan + place ----------------
__global__ void k_hist(const int* __restrict__ col, int e4) {
    int i = blockIdx.x * blockDim.x + threadIdx.x;
    if (i < e4) {
        int4 c = ((const int4*)col)[i];
        atomicAdd(&g_cnt[c.x], 1);
        atomicAdd(&g_cnt[c.y], 1);
        atomicAdd(&g_cnt[c.z], 1);
        atomicAdd(&g_cnt[c.w], 1);
    }
}

// phase 1: per-1024-chunk sums (grid = NB)
__global__ void k_bsum(int n) {
    __shared__ int red[32];
    int i = blockIdx.x * 1024 + threadIdx.x;
    int v = (i < n) ? g_cnt[i] : 0;
    #pragma unroll
    for (int d = 16; d > 0; d >>= 1) v += __shfl_down_sync(0xffffffffu, v, d);
    if ((threadIdx.x & 31) == 0) red[threadIdx.x >> 5] = v;
    __syncthreads();
    if (threadIdx.x < 32) {
        int s = red[threadIdx.x];
        #pragma unroll
        for (int d = 16; d > 0; d >>= 1) s += __shfl_down_sync(0xffffffffu, s, d);
        if (threadIdx.x == 0) g_bsum[blockIdx.x] = s;
    }
}

// phase 2: exclusive scan over NB chunk sums (one tiny block)
__global__ void k_bscan(int nb, int n, int e) {
    __shared__ int s[64];
    int t = threadIdx.x;
    s[t] = (t < nb) ? g_bsum[t] : 0;
    __syncthreads();
    if (t == 0) {
        int run = 0;
        for (int i = 0; i < nb; i++) { int v = s[i]; s[i] = run; run += v; }
        g_off[n] = e;
    }
    __syncthreads();
    if (t < nb) g_bbase[t] = s[t];
}

// phase 3: local exclusive scan per chunk; write off/cur/dis (grid = NB)
__global__ void k_offsets(int n) {
    __shared__ int sbuf[1024];
    int tid = threadIdx.x;
    int i = blockIdx.x * 1024 + tid;
    int c = (i < n) ? g_cnt[i] : 0;
    sbuf[tid] = c;
    __syncthreads();
    // Hillis-Steele inclusive scan
    #pragma unroll
    for (int d = 1; d < 1024; d <<= 1) {
        int t = (tid >= d) ? sbuf[tid - d] : 0;
        __syncthreads();
        sbuf[tid] += t;
        __syncthreads();
    }
    if (i < n) {
        int base = g_bbase[blockIdx.x] + sbuf[tid] - c;   // exclusive
        g_off[i] = base;
        g_cur[i] = base;
        g_dis[i] = rsqrtf((float)(c + 1));
    }
}

__global__ void k_place(const int* __restrict__ row, const int* __restrict__ col, int e4) {
    int i = blockIdx.x * blockDim.x + threadIdx.x;
    if (i < e4) {
        int4 r4 = ((const int4*)row)[i];
        int4 c4 = ((const int4*)col)[i];
        int p;
        p = atomicAdd(&g_cur[c4.x], 1); g_src[p] = r4.x;
        p = atomicAdd(&g_cur[c4.y], 1); g_src[p] = r4.y;
        p = atomicAdd(&g_cur[c4.z], 1); g_src[p] = r4.z;
        p = atomicAdd(&g_cur[c4.w], 1); g_src[p] = r4.w;
    }
}

// ---------------- gathers (warp per node, R5 known-good) ----------------
__global__ void k_gather128(const float* __restrict__ hs, const float* __restrict__ bias,
                            float* __restrict__ outp, int n, int relu) {
    int w = (blockIdx.x * blockDim.x + threadIdx.x) >> 5;
    if (w >= n) return;
    int lane = threadIdx.x & 31;
    const float4* hs4 = (const float4*)hs;
    float dw = g_dis[w];
    float4 self = hs4[(size_t)w * 32 + lane];
    float4 acc = make_float4(self.x * dw, self.y * dw, self.z * dw, self.w * dw);
    int s = g_off[w], e = g_off[w + 1];
    int j = s;
    for (; j + 8 <= e; j += 8) {
        int r[8]; float d[8];
        #pragma unroll
        for (int i = 0; i < 8; i++) r[i] = __ldg(&g_src[j + i]);
        #pragma unroll
        for (int i = 0; i < 8; i++) d[i] = __ldg(&g_dis[r[i]]);
        #pragma unroll
        for (int i = 0; i < 8; i++) {
            float4 m = hs4[(size_t)r[i] * 32 + lane];
            acc.x = fmaf(d[i], m.x, acc.x);
            acc.y = fmaf(d[i], m.y, acc.y);
            acc.z = fmaf(d[i], m.z, acc.z);
            acc.w = fmaf(d[i], m.w, acc.w);
        }
    }
    for (; j < e; j++) {
        int r = __ldg(&g_src[j]);
        float d = __ldg(&g_dis[r]);
        float4 m = hs4[(size_t)r * 32 + lane];
        acc.x = fmaf(d, m.x, acc.x);
        acc.y = fmaf(d, m.y, acc.y);
        acc.z = fmaf(d, m.z, acc.z);
        acc.w = fmaf(d, m.w, acc.w);
    }
    float4 b = ((const float4*)bias)[lane];
    float4 o = make_float4(acc.x * dw + b.x, acc.y * dw + b.y,
                           acc.z * dw + b.z, acc.w * dw + b.w);
    if (relu) {
        o.x = fmaxf(o.x, 0.f); o.y = fmaxf(o.y, 0.f);
        o.z = fmaxf(o.z, 0.f); o.w = fmaxf(o.w, 0.f);
    }
    ((float4*)outp)[(size_t)w * 32 + lane] = o;
}

__global__ void k_gather64(const float* __restrict__ hs, const float* __restrict__ bias,
                           float* __restrict__ outp, int n) {
    int w = (blockIdx.x * blockDim.x + threadIdx.x) >> 5;
    if (w >= n) return;
    int lane = threadIdx.x & 31;
    const float2* hs2 = (const float2*)hs;
    float dw = g_dis[w];
    float2 self = hs2[(size_t)w * 32 + lane];
    float2 acc = make_float2(self.x * dw, self.y * dw);
    int s = g_off[w], e = g_off[w + 1];
    int j = s;
    for (; j + 8 <= e; j += 8) {
        int r[8]; float d[8];
        #pragma unroll
        for (int i = 0; i < 8; i++) r[i] = __ldg(&g_src[j + i]);
        #pragma unroll
        for (int i = 0; i < 8; i++) d[i] = __ldg(&g_dis[r[i]]);
        #pragma unroll
        for (int i = 0; i < 8; i++) {
            float2 m = hs2[(size_t)r[i] * 32 + lane];
            acc.x = fmaf(d[i], m.x, acc.x);
            acc.y = fmaf(d[i], m.y, acc.y);
        }
    }
    for (; j < e; j++) {
        int r = __ldg(&g_src[j]);
        float d = __ldg(&g_dis[r]);
        float2 m = hs2[(size_t)r * 32 + lane];
        acc.x = fmaf(d, m.x, acc.x);
        acc.y = fmaf(d, m.y, acc.y);
    }
    float2 b = ((const float2*)bias)[lane];
    float2 o = make_float2(acc.x * dw + b.x, acc.y * dw + b.y);
    ((float2*)outp)[(size_t)w * 32 + lane] = o;
}

// ---------------- launch ----------------
extern "C" void kernel_launch(void* const* d_in, const int* in_sizes, int n_in,
                              void* d_out, int out_size) {
    const float* x   = (const float*)d_in[0];
    const int*   ei  = (const int*)d_in[1];
    const float* W1  = (const float*)d_in[2];
    const float* b1  = (const float*)d_in[3];
    const float* W2  = (const float*)d_in[4];
    const float* b2  = (const float*)d_in[5];
    float* out = (float*)d_out;

    const int n = in_sizes[0] / DI;     // 50000
    const int e = in_sizes[1] / 2;      // 800000
    const int* row = ei;
    const int* col = ei + e;

    float* B1; float* B2; int* cnt; __half *W1img, *W2img;
    cudaGetSymbolAddress((void**)&B1, g_B1);
    cudaGetSymbolAddress((void**)&B2, g_B2);
    cudaGetSymbolAddress((void**)&cnt, g_cnt);
    cudaGetSymbolAddress((void**)&W1img, g_W1img);
    cudaGetSymbolAddress((void**)&W2img, g_W2img);

    const int SM1 = (2 * 128 * 136 + 2 * 128 * 136) * 2;   // 139264
    const int SM2 = (2 * 128 * 136 + 2 * 64 * 136) * 2;    // 104448
    cudaFuncSetAttribute(k_mgemm<128>, cudaFuncAttributeMaxDynamicSharedMemorySize, SM1);
    cudaFuncSetAttribute(k_mgemm<64>,  cudaFuncAttributeMaxDynamicSharedMemorySize, SM2);

    cudaStream_t s1;
    cudaStreamCreate(&s1);
    cudaEvent_t evFork, evJoin;
    cudaEventCreateWithFlags(&evFork, cudaEventDisableTiming);
    cudaEventCreateWithFlags(&evJoin, cudaEventDisableTiming);

    int nblk = (n + 127) / 128;
    int nb = (n + 1023) / 1024;   // 49 scan chunks

    // side stream: W conversions + GEMM1
    cudaEventRecord(evFork, 0);
    cudaStreamWaitEvent(s1, evFork, 0);
    k_wconv<128><<<1, 256, 0, s1>>>(W1, W1img);
    k_wconv<64><<<1, 256, 0, s1>>>(W2, W2img);
    k_mgemm<128><<<nblk, 256, SM1, s1>>>(x, W1img, B1, n);
    cudaEventRecord(evJoin, s1);

    // capture stream: CSR build with parallel scan
    cudaMemsetAsync(cnt, 0, n * sizeof(int));
    int e4 = e / 4;
    k_hist<<<(e4 + 255) / 256, 256>>>(col, e4);
    k_bsum<<<nb, 1024>>>(n);
    k_bscan<<<1, 64>>>(nb, n, e);
    k_offsets<<<nb, 1024>>>(n);
    k_place<<<(e4 + 255) / 256, 256>>>(row, col, e4);

    cudaStreamWaitEvent(0, evJoin, 0);
    k_gather128<<<(n * 32 + 255) / 256, 256>>>(B1, b1, B2, n, 1);
    k_mgemm<64><<<nblk, 256, SM2>>>(B2, W2img, B1, n);
    k_gather64<<<(n * 32 + 255) / 256, 256>>>(B1, b2, out, n);

    cudaStreamDestroy(s1);
    cudaEventDestroy(evFork);
    cudaEventDestroy(evJoin);
}

// round 8
// speedup vs baseline: 1.4805x; 1.0369x over previous
#include <cuda_runtime.h>
#include <cuda_fp16.h>
#include <math.h>
#include <stdint.h>

#define NN 50000
#define NE 800000
#define DI 128

// ---------------- device scratch ----------------
__device__ __half g_H1[NN * 128];  // hidden h = X@W1, fp16 messages
__device__ float  g_B1[NN * 128];  // GEMM2 out (64-wide), fp32
__device__ float  g_B2[NN * 128];  // y1 = relu(agg1), fp32
__device__ float  g_dis[NN];
__device__ int    g_cnt[NN];
__device__ int    g_off[NN + 1];
__device__ int    g_cur[NN];
__device__ int    g_src[NE];
__device__ int    g_bsum[64];
__device__ int    g_bbase[64];
// W images: fp16 split, [n][k] row-major, stride 136 halves; hi tile then lo tile
__device__ __align__(16) __half g_W1img[2 * 128 * 136];
__device__ __align__(16) __half g_W2img[2 * 64 * 136];

__device__ __forceinline__ uint32_t smem_u32(const void* p) {
    uint32_t a;
    asm("{ .reg .u64 t; cvta.to.shared.u64 t, %1; cvt.u32.u64 %0, t; }" : "=r"(a) : "l"(p));
    return a;
}

#define LDSM_X4(r0, r1, r2, r3, addr) \
    asm volatile("ldmatrix.sync.aligned.m8n8.x4.shared.b16 {%0,%1,%2,%3}, [%4];" \
                 : "=r"(r0), "=r"(r1), "=r"(r2), "=r"(r3) : "r"(addr))
#define LDSM_X2(r0, r1, addr) \
    asm volatile("ldmatrix.sync.aligned.m8n8.x2.shared.b16 {%0,%1}, [%2];" \
                 : "=r"(r0), "=r"(r1) : "r"(addr))

__device__ __forceinline__ void mma16816(float* c, const uint32_t* a, const uint32_t* b) {
    asm volatile(
        "mma.sync.aligned.m16n8k16.row.col.f32.f16.f16.f32 "
        "{%0,%1,%2,%3}, {%4,%5,%6,%7}, {%8,%9}, {%0,%1,%2,%3};"
        : "+f"(c[0]), "+f"(c[1]), "+f"(c[2]), "+f"(c[3])
        : "r"(a[0]), "r"(a[1]), "r"(a[2]), "r"(a[3]), "r"(b[0]), "r"(b[1]));
}

// ---------------- W image precompute ----------------
template<int NOUT>
__global__ void k_wconv(const float* __restrict__ W, __half* __restrict__ img) {
    constexpr int S = 136;
    int tid = threadIdx.x;
    for (int idx = tid; idx < NOUT * 128; idx += 256) {
        int nn = idx % NOUT;
        int k  = idx / NOUT;
        float v = W[k * NOUT + nn];
        __half h = __float2half_rn(v);
        __half l = __float2half_rn(v - __half2float(h));
        img[nn * S + k] = h;
        img[NOUT * S + nn * S + k] = l;
    }
}

// ---------------- tensor GEMM via mma.sync, 3-term fp16 split ----------------
// HOUT=true: store output as fp16 (half2 pairs); false: fp32.
template<int NOUT, bool HOUT>
__global__ void __launch_bounds__(256, 1) k_mgemm(const float* __restrict__ A,
                                                  const __half* __restrict__ Wimg,
                                                  void* __restrict__ outp, int n) {
    constexpr int S = 136;
    constexpr int SB = S * 2;
    constexpr int ASZ = 128 * S;
    constexpr int BSZ = NOUT * S;
    constexpr int MI = (NOUT == 128) ? 4 : 2;

    extern __shared__ __half sm[];
    __half* Ah = sm;
    __half* Al = sm + ASZ;
    __half* Bh = sm + 2 * ASZ;
    __half* Bl = sm + 2 * ASZ + BSZ;

    int tid = threadIdx.x, wid = tid >> 5, lane = tid & 31;
    int row0 = blockIdx.x * 128;

    {
        const uint4* src = (const uint4*)Wimg;
        uint4* dst = (uint4*)Bh;
        for (int i = tid; i < (2 * BSZ) / 8; i += 256) dst[i] = src[i];
    }
    {
        const float4* A4 = (const float4*)A;
        #pragma unroll
        for (int i = 0; i < 16; i++) {
            int idx = tid + i * 256;
            int r = idx >> 5;
            int c = idx & 31;
            float4 v = make_float4(0.f, 0.f, 0.f, 0.f);
            if (row0 + r < n) v = A4[(size_t)(row0 + r) * 32 + c];
            __half h0 = __float2half_rn(v.x), h1 = __float2half_rn(v.y);
            __half h2 = __float2half_rn(v.z), h3 = __float2half_rn(v.w);
            __half l0 = __float2half_rn(v.x - __half2float(h0));
            __half l1 = __float2half_rn(v.y - __half2float(h1));
            __half l2 = __float2half_rn(v.z - __half2float(h2));
            __half l3 = __float2half_rn(v.w - __half2float(h3));
            __half2 hp0 = __halves2half2(h0, h1), hp1 = __halves2half2(h2, h3);
            __half2 lp0 = __halves2half2(l0, l1), lp1 = __halves2half2(l2, l3);
            *(uint2*)&Ah[r * S + c * 4] = make_uint2(*(uint32_t*)&hp0, *(uint32_t*)&hp1);
            *(uint2*)&Al[r * S + c * 4] = make_uint2(*(uint32_t*)&lp0, *(uint32_t*)&lp1);
        }
    }
    __syncthreads();

    int m0w, n0w;
    if (NOUT == 128) { m0w = (wid >> 2) * 64; n0w = (wid & 3) * 32; }
    else             { m0w = (wid >> 1) * 32; n0w = (wid & 1) * 32; }

    float acc[MI][4][4] = {};

    uint32_t aAh = smem_u32(Ah), aAl = smem_u32(Al);
    uint32_t aBh = smem_u32(Bh), aBl = smem_u32(Bl);
    uint32_t a_lane = (uint32_t)(m0w + (lane & 15)) * SB + ((lane >> 4) << 4);
    int bl = lane & 15;
    uint32_t b_lane = (uint32_t)(n0w + (bl & 7)) * SB + ((bl >> 3) << 4);

    #pragma unroll
    for (int t = 0; t < 3; t++) {
        uint32_t aA = (t == 2) ? aAl : aAh;
        uint32_t aB = (t == 1) ? aBl : aBh;
        #pragma unroll
        for (int k0 = 0; k0 < 128; k0 += 16) {
            uint32_t ar[MI][4];
            #pragma unroll
            for (int mi = 0; mi < MI; mi++) {
                uint32_t ad = aA + a_lane + (uint32_t)(mi * 16) * SB + k0 * 2;
                LDSM_X4(ar[mi][0], ar[mi][1], ar[mi][2], ar[mi][3], ad);
            }
            #pragma unroll
            for (int nj = 0; nj < 4; nj++) {
                uint32_t br[2];
                uint32_t bd = aB + b_lane + (uint32_t)(nj * 8) * SB + k0 * 2;
                LDSM_X2(br[0], br[1], bd);
                #pragma unroll
                for (int mi = 0; mi < MI; mi++) mma16816(acc[mi][nj], ar[mi], br);
            }
        }
    }

    #pragma unroll
    for (int mi = 0; mi < MI; mi++) {
        int r = row0 + m0w + mi * 16 + (lane >> 2);
        #pragma unroll
        for (int nj = 0; nj < 4; nj++) {
            int c = n0w + nj * 8 + (lane & 3) * 2;   // always even
            if (HOUT) {
                __half* O = (__half*)outp;
                if (r < n) {
                    __half2 p = __floats2half2_rn(acc[mi][nj][0], acc[mi][nj][1]);
                    *(uint32_t*)&O[(size_t)r * NOUT + c] = *(uint32_t*)&p;
                }
                if (r + 8 < n) {
                    __half2 p = __floats2half2_rn(acc[mi][nj][2], acc[mi][nj][3]);
                    *(uint32_t*)&O[(size_t)(r + 8) * NOUT + c] = *(uint32_t*)&p;
                }
            } else {
                float* O = (float*)outp;
                if (r < n)
                    *(float2*)&O[(size_t)r * NOUT + c] = make_float2(acc[mi][nj][0], acc[mi][nj][1]);
                if (r + 8 < n)
                    *(float2*)&O[(size_t)(r + 8) * NOUT + c] = make_float2(acc[mi][nj][2], acc[mi][nj][3]);
            }
        }
    }
}

// ---------------- CSR build: hist + 3-phase parallel scan + place ----------------
__global__ void k_hist(const int* __restrict__ col, int e4) {
    int i = blockIdx.x * blockDim.x + threadIdx.x;
    if (i < e4) {
        int4 c = ((const int4*)col)[i];
        atomicAdd(&g_cnt[c.x], 1);
        atomicAdd(&g_cnt[c.y], 1);
        atomicAdd(&g_cnt[c.z], 1);
        atomicAdd(&g_cnt[c.w], 1);
    }
}

__global__ void k_bsum(int n) {
    __shared__ int red[32];
    int i = blockIdx.x * 1024 + threadIdx.x;
    int v = (i < n) ? g_cnt[i] : 0;
    #pragma unroll
    for (int d = 16; d > 0; d >>= 1) v += __shfl_down_sync(0xffffffffu, v, d);
    if ((threadIdx.x & 31) == 0) red[threadIdx.x >> 5] = v;
    __syncthreads();
    if (threadIdx.x < 32) {
        int s = red[threadIdx.x];
        #pragma unroll
        for (int d = 16; d > 0; d >>= 1) s += __shfl_down_sync(0xffffffffu, s, d);
        if (threadIdx.x == 0) g_bsum[blockIdx.x] = s;
    }
}

__global__ void k_bscan(int nb, int n, int e) {
    __shared__ int s[64];
    int t = threadIdx.x;
    s[t] = (t < nb) ? g_bsum[t] : 0;
    __syncthreads();
    if (t == 0) {
        int run = 0;
        for (int i = 0; i < nb; i++) { int v = s[i]; s[i] = run; run += v; }
        g_off[n] = e;
    }
    __syncthreads();
    if (t < nb) g_bbase[t] = s[t];
}

__global__ void k_offsets(int n) {
    __shared__ int sbuf[1024];
    int tid = threadIdx.x;
    int i = blockIdx.x * 1024 + tid;
    int c = (i < n) ? g_cnt[i] : 0;
    sbuf[tid] = c;
    __syncthreads();
    #pragma unroll
    for (int d = 1; d < 1024; d <<= 1) {
        int t = (tid >= d) ? sbuf[tid - d] : 0;
        __syncthreads();
        sbuf[tid] += t;
        __syncthreads();
    }
    if (i < n) {
        int base = g_bbase[blockIdx.x] + sbuf[tid] - c;
        g_off[i] = base;
        g_cur[i] = base;
        g_dis[i] = rsqrtf((float)(c + 1));
    }
}

__global__ void k_place(const int* __restrict__ row, const int* __restrict__ col, int e4) {
    int i = blockIdx.x * blockDim.x + threadIdx.x;
    if (i < e4) {
        int4 r4 = ((const int4*)row)[i];
        int4 c4 = ((const int4*)col)[i];
        int p;
        p = atomicAdd(&g_cur[c4.x], 1); g_src[p] = r4.x;
        p = atomicAdd(&g_cur[c4.y], 1); g_src[p] = r4.y;
        p = atomicAdd(&g_cur[c4.z], 1); g_src[p] = r4.z;
        p = atomicAdd(&g_cur[c4.w], 1); g_src[p] = r4.w;
    }
}

// ---------------- gather layer1 (warp per node), fp16 messages, fp32 accumulate ----------------
__global__ void k_gather128h(const __half* __restrict__ hs, const float* __restrict__ bias,
                             float* __restrict__ outp, int n) {
    int w = (blockIdx.x * blockDim.x + threadIdx.x) >> 5;
    if (w >= n) return;
    int lane = threadIdx.x & 31;
    const uint2* hs2 = (const uint2*)hs;    // 4 halves per uint2; 32 uint2 per row
    float dw = g_dis[w];
    uint2 sv = hs2[(size_t)w * 32 + lane];
    float2 s01 = __half22float2(*(__half2*)&sv.x);
    float2 s23 = __half22float2(*(__half2*)&sv.y);
    float4 acc = make_float4(s01.x * dw, s01.y * dw, s23.x * dw, s23.y * dw);
    int s = g_off[w], e = g_off[w + 1];
    int j = s;
    for (; j + 8 <= e; j += 8) {
        int r[8]; float d[8];
        #pragma unroll
        for (int i = 0; i < 8; i++) r[i] = __ldg(&g_src[j + i]);
        #pragma unroll
        for (int i = 0; i < 8; i++) d[i] = __ldg(&g_dis[r[i]]);
        #pragma unroll
        for (int i = 0; i < 8; i++) {
            uint2 mv = hs2[(size_t)r[i] * 32 + lane];
            float2 m01 = __half22float2(*(__half2*)&mv.x);
            float2 m23 = __half22float2(*(__half2*)&mv.y);
            acc.x = fmaf(d[i], m01.x, acc.x);
            acc.y = fmaf(d[i], m01.y, acc.y);
            acc.z = fmaf(d[i], m23.x, acc.z);
            acc.w = fmaf(d[i], m23.y, acc.w);
        }
    }
    for (; j < e; j++) {
        int r = __ldg(&g_src[j]);
        float d = __ldg(&g_dis[r]);
        uint2 mv = hs2[(size_t)r * 32 + lane];
        float2 m01 = __half22float2(*(__half2*)&mv.x);
        float2 m23 = __half22float2(*(__half2*)&mv.y);
        acc.x = fmaf(d, m01.x, acc.x);
        acc.y = fmaf(d, m01.y, acc.y);
        acc.z = fmaf(d, m23.x, acc.z);
        acc.w = fmaf(d, m23.y, acc.w);
    }
    float4 b = ((const float4*)bias)[lane];
    float4 o = make_float4(fmaxf(acc.x * dw + b.x, 0.f), fmaxf(acc.y * dw + b.y, 0.f),
                           fmaxf(acc.z * dw + b.z, 0.f), fmaxf(acc.w * dw + b.w, 0.f));
    ((float4*)outp)[(size_t)w * 32 + lane] = o;
}

// ---------------- gather layer2 (warp per node, 64-wide, fp32) ----------------
__global__ void k_gather64(const float* __restrict__ hs, const float* __restrict__ bias,
                           float* __restrict__ outp, int n) {
    int w = (blockIdx.x * blockDim.x + threadIdx.x) >> 5;
    if (w >= n) return;
    int lane = threadIdx.x & 31;
    const float2* hs2 = (const float2*)hs;
    float dw = g_dis[w];
    float2 self = hs2[(size_t)w * 32 + lane];
    float2 acc = make_float2(self.x * dw, self.y * dw);
    int s = g_off[w], e = g_off[w + 1];
    int j = s;
    for (; j + 8 <= e; j += 8) {
        int r[8]; float d[8];
        #pragma unroll
        for (int i = 0; i < 8; i++) r[i] = __ldg(&g_src[j + i]);
        #pragma unroll
        for (int i = 0; i < 8; i++) d[i] = __ldg(&g_dis[r[i]]);
        #pragma unroll
        for (int i = 0; i < 8; i++) {
            float2 m = hs2[(size_t)r[i] * 32 + lane];
            acc.x = fmaf(d[i], m.x, acc.x);
            acc.y = fmaf(d[i], m.y, acc.y);
        }
    }
    for (; j < e; j++) {
        int r = __ldg(&g_src[j]);
        float d = __ldg(&g_dis[r]);
        float2 m = hs2[(size_t)r * 32 + lane];
        acc.x = fmaf(d, m.x, acc.x);
        acc.y = fmaf(d, m.y, acc.y);
    }
    float2 b = ((const float2*)bias)[lane];
    float2 o = make_float2(acc.x * dw + b.x, acc.y * dw + b.y);
    ((float2*)outp)[(size_t)w * 32 + lane] = o;
}

// ---------------- launch ----------------
extern "C" void kernel_launch(void* const* d_in, const int* in_sizes, int n_in,
                              void* d_out, int out_size) {
    const float* x   = (const float*)d_in[0];
    const int*   ei  = (const int*)d_in[1];
    const float* W1  = (const float*)d_in[2];
    const float* b1  = (const float*)d_in[3];
    const float* W2  = (const float*)d_in[4];
    const float* b2  = (const float*)d_in[5];
    float* out = (float*)d_out;

    const int n = in_sizes[0] / DI;     // 50000
    const int e = in_sizes[1] / 2;      // 800000
    const int* row = ei;
    const int* col = ei + e;

    __half* H1; float* B1; float* B2; int* cnt; __half *W1img, *W2img;
    cudaGetSymbolAddress((void**)&H1, g_H1);
    cudaGetSymbolAddress((void**)&B1, g_B1);
    cudaGetSymbolAddress((void**)&B2, g_B2);
    cudaGetSymbolAddress((void**)&cnt, g_cnt);
    cudaGetSymbolAddress((void**)&W1img, g_W1img);
    cudaGetSymbolAddress((void**)&W2img, g_W2img);

    const int SM1 = (2 * 128 * 136 + 2 * 128 * 136) * 2;   // 139264
    const int SM2 = (2 * 128 * 136 + 2 * 64 * 136) * 2;    // 104448
    cudaFuncSetAttribute((const void*)k_mgemm<128, true>,
                         cudaFuncAttributeMaxDynamicSharedMemorySize, SM1);
    cudaFuncSetAttribute((const void*)k_mgemm<64, false>,
                         cudaFuncAttributeMaxDynamicSharedMemorySize, SM2);

    cudaStream_t s1;
    cudaStreamCreate(&s1);
    cudaEvent_t evFork, evJoin;
    cudaEventCreateWithFlags(&evFork, cudaEventDisableTiming);
    cudaEventCreateWithFlags(&evJoin, cudaEventDisableTiming);

    int nblk = (n + 127) / 128;
    int nb = (n + 1023) / 1024;

    // side stream: W conversions + GEMM1 (fp16 output)
    cudaEventRecord(evFork, 0);
    cudaStreamWaitEvent(s1, evFork, 0);
    k_wconv<128><<<1, 256, 0, s1>>>(W1, W1img);
    k_wconv<64><<<1, 256, 0, s1>>>(W2, W2img);
    k_mgemm<128, true><<<nblk, 256, SM1, s1>>>(x, W1img, H1, n);
    cudaEventRecord(evJoin, s1);

    // capture stream: CSR build with parallel scan
    cudaMemsetAsync(cnt, 0, n * sizeof(int));
    int e4 = e / 4;
    k_hist<<<(e4 + 255) / 256, 256>>>(col, e4);
    k_bsum<<<nb, 1024>>>(n);
    k_bscan<<<1, 64>>>(nb, n, e);
    k_offsets<<<nb, 1024>>>(n);
    k_place<<<(e4 + 255) / 256, 256>>>(row, col, e4);

    cudaStreamWaitEvent(0, evJoin, 0);
    k_gather128h<<<(n * 32 + 255) / 256, 256>>>(H1, b1, B2, n);
    k_mgemm<64, false><<<nblk, 256, SM2>>>(B2, W2img, B1, n);
    k_gather64<<<(n * 32 + 255) / 256, 256>>>(B1, b2, out, n);

    cudaStreamDestroy(s1);
    cudaEventDestroy(evFork);
    cudaEventDestroy(evJoin);
}